// round 8
// baseline (speedup 1.0000x reference)
#include <cuda_runtime.h>
#include <cstddef>

#define TT   1024
#define BB   64
#define FF   512          // feature dim (== 2H, so both layers share K=512)
#define HH   256
#define GXN  1280         // 5*H
#define NBLK 128          // recurrence blocks: 2 dirs * 64 slices

// ---------------- scratch (device globals; no runtime allocation) ------------
__device__ float g_x  [(size_t)TT*BB*FF];        // layer-0 input, time-major [t][b][512]
__device__ float g_y  [(size_t)TT*BB*FF];        // layer-0 output / layer-1 input
__device__ float g_fin[(size_t)TT*BB*FF];        // layer-1 output
__device__ float g_gx [2][(size_t)TT*BB*GXN];    // per-dir input-gate projections
__device__ float g_px [2][(size_t)TT*BB*HH];     // per-dir highway projections
__device__ float g_h  [2][2][HH*BB];             // [parity][dir][k][b] hidden exchange
__device__ unsigned g_bar;

// ---------------- transpose: features [b][t][512] -> x [t][b][512] -----------
__global__ void k_tin(const float* __restrict__ feat, float* __restrict__ x) {
    int row = blockIdx.x;               // b*T + t
    int b = row >> 10, t = row & 1023;
    const float4* s = (const float4*)(feat + (size_t)row * FF);
    float4* d = (float4*)(x + ((size_t)t * BB + b) * FF);
    for (int i = threadIdx.x; i < FF / 4; i += blockDim.x) d[i] = s[i];
}

// ---------------- transpose: fin [t][b][512] -> out [b][t][512] --------------
__global__ void k_tout(const float* __restrict__ fin, float* __restrict__ out) {
    int row = blockIdx.x;               // t*B + b
    int t = row >> 6, b = row & 63;
    const float4* s = (const float4*)(fin + (size_t)row * FF);
    float4* d = (float4*)(out + (((size_t)b << 10) + t) * FF);
    for (int i = threadIdx.x; i < FF / 4; i += blockDim.x) d[i] = s[i];
}

// ---------------- SGEMM: C[M,N] = A[M,K] @ W[K,N] + bias[N] ------------------
// M=65536 (div 128), K=512 (div 16), N in {1280,256} (div 128). No guards needed.
#define BM 128
#define BN 128
#define BK 16
#define PA 132   // padded A pitch in smem

__global__ __launch_bounds__(256, 2)
void k_gemm(const float* __restrict__ A, const float* __restrict__ W,
            const float* __restrict__ bias, float* __restrict__ C,
            int N, int K) {
    __shared__ float As[BK * PA];   // As[k][m]
    __shared__ float Bs[BK * BN];   // Bs[k][n]
    int tid = threadIdx.x;
    int m0 = blockIdx.y * BM;
    int n0 = blockIdx.x * BN;
    int tx = tid & 15, ty = tid >> 4;

    float acc[8][8];
#pragma unroll
    for (int i = 0; i < 8; i++)
#pragma unroll
        for (int j = 0; j < 8; j++) acc[i][j] = 0.f;

    for (int k0 = 0; k0 < K; k0 += BK) {
#pragma unroll
        for (int it = 0; it < 2; it++) {      // A tile: 128 rows x 16 k
            int idx = tid + it * 256;
            int row = idx >> 2, kq = idx & 3;
            float4 v = *(const float4*)(A + (size_t)(m0 + row) * K + k0 + kq * 4);
            As[(kq * 4 + 0) * PA + row] = v.x;
            As[(kq * 4 + 1) * PA + row] = v.y;
            As[(kq * 4 + 2) * PA + row] = v.z;
            As[(kq * 4 + 3) * PA + row] = v.w;
        }
#pragma unroll
        for (int it = 0; it < 2; it++) {      // B tile: 16 k x 128 n
            int idx = tid + it * 256;
            int kk = idx >> 5, nq = idx & 31;
            *(float4*)(Bs + kk * BN + nq * 4) =
                *(const float4*)(W + (size_t)(k0 + kk) * N + n0 + nq * 4);
        }
        __syncthreads();
#pragma unroll
        for (int kk = 0; kk < BK; kk++) {
            float a[8], bfr[8];
            *(float4*)(a)     = *(const float4*)(As + kk * PA + ty * 8);
            *(float4*)(a + 4) = *(const float4*)(As + kk * PA + ty * 8 + 4);
            *(float4*)(bfr)     = *(const float4*)(Bs + kk * BN + tx * 8);
            *(float4*)(bfr + 4) = *(const float4*)(Bs + kk * BN + tx * 8 + 4);
#pragma unroll
            for (int i = 0; i < 8; i++)
#pragma unroll
                for (int j = 0; j < 8; j++) acc[i][j] += a[i] * bfr[j];
        }
        __syncthreads();
    }

    float bv[8];
    *(float4*)(bv)     = *(const float4*)(bias + n0 + tx * 8);
    *(float4*)(bv + 4) = *(const float4*)(bias + n0 + tx * 8 + 4);
#pragma unroll
    for (int i = 0; i < 8; i++) {
        size_t off = (size_t)(m0 + ty * 8 + i) * N + n0 + tx * 8;
        float4 v0 = {acc[i][0] + bv[0], acc[i][1] + bv[1], acc[i][2] + bv[2], acc[i][3] + bv[3]};
        float4 v1 = {acc[i][4] + bv[4], acc[i][5] + bv[5], acc[i][6] + bv[6], acc[i][7] + bv[7]};
        *(float4*)(C + off)     = v0;
        *(float4*)(C + off + 4) = v1;
    }
}

// ---------------- reset barrier + h buffers (before each recurrence) ---------
__global__ void k_reset() {
    int i = blockIdx.x * blockDim.x + threadIdx.x;
    if (i == 0) g_bar = 0u;
    float* gh = &g_h[0][0][0];
    if (i < 2 * 2 * HH * BB) gh[i] = 0.f;
}

// ---------------- persistent bidirectional highway-LSTM scan -----------------
// grid = 128 blocks: blockIdx.x = d + 2*j  (d: direction, j: 4-col slice 0..63)
// block = 128 threads: c = tid&3 (col within slice), bq = (tid>>2)&15 (4-batch
// group), kh = tid>>6 (k half for split reduction).
// Per step: z = gx[t] + h@Wh + bh; gates; double-buffered h in L2; one grid
// barrier per step (monotonic atomic counter, all 128 blocks wave-1 resident).
#define REC_SMEM ((256 * 20 + 256 * 64) * 4)

__device__ __forceinline__ float sigf(float x) { return 1.f / (1.f + expf(-x)); }

__global__ __launch_bounds__(128, 1)
void k_rec(const float* __restrict__ Wh_l,   // [2][256][1280] (this layer)
           const float* __restrict__ bh_l,   // [2][1280]
           const float* __restrict__ gx0, const float* __restrict__ gx1,
           const float* __restrict__ px0, const float* __restrict__ px1,
           float* __restrict__ outbuf) {     // [t][b][512] (fwd|bwd concat)
    extern __shared__ float sm[];
    float* w_s = sm;                 // [256][20] Wh slice (gate-interleaved)
    float* h_s = sm + 256 * 20;      // [256 k][64 b] staged h_prev
    float* red = h_s;                // reused post-k-loop for kh reduction

    int tid = threadIdx.x;
    int d  = blockIdx.x & 1;
    int j  = blockIdx.x >> 1;
    int c  = tid & 3;
    int bq = (tid >> 2) & 15;
    int kh = tid >> 6;
    int col = j * 4 + c;
    int b0  = bq * 4;
    int be  = b0 + kh * 2;           // epilogue batches: be, be+1

    const float* Wh_d = Wh_l + (size_t)d * HH * GXN;
    const float* gx = d ? gx1 : gx0;
    const float* px = d ? px1 : px0;

    for (int idx = tid; idx < 256 * 20; idx += 128) {
        int k = idx / 20, gc = idx % 20;
        int g = gc >> 2, cc = gc & 3;
        w_s[idx] = Wh_d[(size_t)k * GXN + g * HH + j * 4 + cc];
    }
    float bh5[5];
#pragma unroll
    for (int g = 0; g < 5; g++) bh5[g] = bh_l[(size_t)d * GXN + g * HH + col];

    float cs0 = 0.f, cs1 = 0.f;      // cell states for be, be+1
    __syncthreads();

    for (int s = 0; s < TT; s++) {
        int t = d ? (TT - 1 - s) : s;

        // prefetch gate inputs for the epilogue (resolve during k-loop)
        size_t r0 = ((size_t)t * BB + be) * GXN;
        float gxa[5], gxb[5];
#pragma unroll
        for (int g = 0; g < 5; g++) {
            gxa[g] = __ldg(gx + r0 + g * HH + col);
            gxb[g] = __ldg(gx + r0 + GXN + g * HH + col);
        }
        float pxa = __ldg(px + ((size_t)t * BB + be) * HH + col);
        float pxb = __ldg(px + ((size_t)t * BB + be + 1) * HH + col);

        // stage h_prev (written by all slice-blocks last step) via L2
        {
            const float4* src = (const float4*)&g_h[s & 1][d][0];
            float4* dst = (float4*)h_s;
#pragma unroll
            for (int i = 0; i < 32; i++) dst[tid + i * 128] = __ldcg(&src[tid + i * 128]);
        }
        __syncthreads();

        float4 acc[5];
#pragma unroll
        for (int g = 0; g < 5; g++) acc[g] = make_float4(0.f, 0.f, 0.f, 0.f);
        int kb = kh * 128;
#pragma unroll 4
        for (int k = 0; k < 128; k++) {
            float4 hv = *(const float4*)&h_s[(kb + k) * BB + b0];
#pragma unroll
            for (int g = 0; g < 5; g++) {
                float w = w_s[(kb + k) * 20 + g * 4 + c];
                acc[g].x += hv.x * w;
                acc[g].y += hv.y * w;
                acc[g].z += hv.z * w;
                acc[g].w += hv.w * w;
            }
        }
        __syncthreads();                       // h_s no longer needed -> red

        // exchange the 2 components the partner kh-thread finalizes
        int slot = (bq * 4 + c) * 10;
        float* myred = red + kh * 640 + slot;
        if (kh == 0) {
#pragma unroll
            for (int g = 0; g < 5; g++) { myred[g * 2] = acc[g].z; myred[g * 2 + 1] = acc[g].w; }
        } else {
#pragma unroll
            for (int g = 0; g < 5; g++) { myred[g * 2] = acc[g].x; myred[g * 2 + 1] = acc[g].y; }
        }
        __syncthreads();
        const float* pr = red + (1 - kh) * 640 + slot;
        float za[5], zb[5];
        if (kh == 0) {
#pragma unroll
            for (int g = 0; g < 5; g++) { za[g] = acc[g].x + pr[g * 2]; zb[g] = acc[g].y + pr[g * 2 + 1]; }
        } else {
#pragma unroll
            for (int g = 0; g < 5; g++) { za[g] = acc[g].z + pr[g * 2]; zb[g] = acc[g].w + pr[g * 2 + 1]; }
        }

        // gates: z split order = i, o, f, u, r
        {
            float zi = za[0] + gxa[0] + bh5[0];
            float zo = za[1] + gxa[1] + bh5[1];
            float zf = za[2] + gxa[2] + bh5[2];
            float zu = za[3] + gxa[3] + bh5[3];
            float zr = za[4] + gxa[4] + bh5[4];
            cs0 = sigf(zi) * tanhf(zu) + sigf(zf) * cs0;
            float hhv = sigf(zo) * tanhf(cs0);
            float rg  = sigf(zr);
            float hf  = rg * hhv + (1.f - rg) * pxa;
            __stcg(&g_h[(s + 1) & 1][d][col * BB + be], hf);
            outbuf[((size_t)t * BB + be) * FF + d * HH + col] = hf;
        }
        {
            float zi = zb[0] + gxb[0] + bh5[0];
            float zo = zb[1] + gxb[1] + bh5[1];
            float zf = zb[2] + gxb[2] + bh5[2];
            float zu = zb[3] + gxb[3] + bh5[3];
            float zr = zb[4] + gxb[4] + bh5[4];
            cs1 = sigf(zi) * tanhf(zu) + sigf(zf) * cs1;
            float hhv = sigf(zo) * tanhf(cs1);
            float rg  = sigf(zr);
            float hf  = rg * hhv + (1.f - rg) * pxb;
            __stcg(&g_h[(s + 1) & 1][d][col * BB + be + 1], hf);
            outbuf[((size_t)t * BB + be + 1) * FF + d * HH + col] = hf;
        }

        // grid barrier: make h stores visible, arrive, spin on monotonic count
        __threadfence();
        __syncthreads();
        if (tid == 0) {
            atomicAdd(&g_bar, 1u);
            unsigned target = (unsigned)(s + 1) * NBLK;
            volatile unsigned* vb = &g_bar;
            while (*vb < target) __nanosleep(40);
        }
        __syncthreads();
    }
}

// ---------------------------- host driver ------------------------------------
extern "C" void kernel_launch(void* const* d_in, const int* in_sizes, int n_in,
                              void* d_out, int out_size) {
    (void)in_sizes; (void)n_in; (void)out_size;
    const float* feat = (const float*)d_in[0];
    const float* Wx   = (const float*)d_in[1];  // [2][2][512][1280]
    const float* bx   = (const float*)d_in[2];  // [2][2][1280]
    const float* Wh   = (const float*)d_in[3];  // [2][2][256][1280]
    const float* bh   = (const float*)d_in[4];  // [2][2][1280]
    const float* Wp   = (const float*)d_in[5];  // [2][2][512][256]
    const float* bp   = (const float*)d_in[6];  // [2][2][256]
    float* out = (float*)d_out;

    float *p_x, *p_y, *p_f, *p_gx, *p_px;
    cudaGetSymbolAddress((void**)&p_x,  g_x);
    cudaGetSymbolAddress((void**)&p_y,  g_y);
    cudaGetSymbolAddress((void**)&p_f,  g_fin);
    cudaGetSymbolAddress((void**)&p_gx, g_gx);
    cudaGetSymbolAddress((void**)&p_px, g_px);

    cudaFuncSetAttribute(k_rec, cudaFuncAttributeMaxDynamicSharedMemorySize, REC_SMEM);

    const size_t GXSZ = (size_t)TT * BB * GXN;
    const size_t PXSZ = (size_t)TT * BB * HH;

    k_tin<<<TT * BB, 128>>>(feat, p_x);

    for (int l = 0; l < 2; l++) {
        const float* X = l ? p_y : p_x;
        float* OUT = l ? p_f : p_y;
        for (int dd = 0; dd < 2; dd++) {
            int w = l * 2 + dd;
            k_gemm<<<dim3(GXN / 128, (TT * BB) / 128), 256>>>(
                X, Wx + (size_t)w * FF * GXN, bx + (size_t)w * GXN,
                p_gx + dd * GXSZ, GXN, FF);
            k_gemm<<<dim3(HH / 128, (TT * BB) / 128), 256>>>(
                X, Wp + (size_t)w * FF * HH, bp + (size_t)w * HH,
                p_px + dd * PXSZ, HH, FF);
        }
        k_reset<<<256, 256>>>();
        k_rec<<<NBLK, 128, REC_SMEM>>>(
            Wh + (size_t)l * 2 * HH * GXN, bh + (size_t)l * 2 * GXN,
            p_gx, p_gx + GXSZ, p_px, p_px + PXSZ, OUT);
    }

    k_tout<<<TT * BB, 128>>>(p_f, out);
}

// round 10
// speedup vs baseline: 1.3870x; 1.3870x over previous
#include <cuda_runtime.h>
#include <cuda_bf16.h>
#include <cstddef>
#include <cstdint>

#define TT   1024
#define BB   64
#define FF   512          // feature dim (== 2H, both layers share K=512)
#define HH   256
#define GXN  1280         // 5*H
#define NBLK 128          // recurrence blocks: 2 dirs * 64 slices

// ---------------- scratch (device globals; no runtime allocation) ------------
__device__ float g_y  [(size_t)TT*BB*FF];        // layer-0 output / layer-1 input (fp32)
__device__ float g_fin[(size_t)TT*BB*FF];        // layer-1 output
__device__ float g_gx [2][(size_t)TT*BB*GXN];    // per-dir input-gate projections
__device__ float g_px [2][(size_t)TT*BB*HH];     // per-dir highway projections
__device__ float g_h  [2][2][HH*BB];             // [parity][dir][k][b] hidden exchange
__device__ unsigned g_bar;

// bf16 split operands
__device__ __nv_bfloat16 g_xh[(size_t)TT*BB*FF], g_xl[(size_t)TT*BB*FF];
__device__ __nv_bfloat16 g_yh[(size_t)TT*BB*FF], g_yl[(size_t)TT*BB*FF];
__device__ __nv_bfloat16 g_wxh[2*2*FF*GXN], g_wxl[2*2*FF*GXN];
__device__ __nv_bfloat16 g_wph[2*2*FF*HH],  g_wpl[2*2*FF*HH];

// ---------------- helpers ----------------------------------------------------
__device__ __forceinline__ void split1(float x, __nv_bfloat16& h, __nv_bfloat16& l) {
    h = __float2bfloat16(x);
    l = __float2bfloat16(x - __bfloat162float(h));
}

// transpose+split: features [b][t][512] fp32 -> xh/xl [t][b][512] bf16
__global__ void k_tin(const float* __restrict__ feat,
                      __nv_bfloat16* __restrict__ xh, __nv_bfloat16* __restrict__ xl) {
    int row = blockIdx.x;               // b*T + t
    int b = row >> 10, t = row & 1023;
    float4 v = ((const float4*)(feat + (size_t)row * FF))[threadIdx.x];
    size_t drow = ((size_t)t * BB + b) * FF + threadIdx.x * 4;
    __nv_bfloat16 h4[4], l4[4];
    split1(v.x, h4[0], l4[0]); split1(v.y, h4[1], l4[1]);
    split1(v.z, h4[2], l4[2]); split1(v.w, h4[3], l4[3]);
    *(uint2*)(xh + drow) = *(uint2*)h4;
    *(uint2*)(xl + drow) = *(uint2*)l4;
}

// generic fp32 -> bf16 hi/lo split (n4 = element count / 4)
__global__ void k_split(const float* __restrict__ in,
                        __nv_bfloat16* __restrict__ hi, __nv_bfloat16* __restrict__ lo, int n4) {
    int i = blockIdx.x * blockDim.x + threadIdx.x;
    if (i >= n4) return;
    float4 v = ((const float4*)in)[i];
    __nv_bfloat16 h4[4], l4[4];
    split1(v.x, h4[0], l4[0]); split1(v.y, h4[1], l4[1]);
    split1(v.z, h4[2], l4[2]); split1(v.w, h4[3], l4[3]);
    *(uint2*)(hi + (size_t)i * 4) = *(uint2*)h4;
    *(uint2*)(lo + (size_t)i * 4) = *(uint2*)l4;
}

// transpose: fin [t][b][512] -> out [b][t][512]
__global__ void k_tout(const float* __restrict__ fin, float* __restrict__ out) {
    int row = blockIdx.x;               // t*B + b
    int t = row >> 6, b = row & 63;
    const float4* s = (const float4*)(fin + (size_t)row * FF);
    float4* d = (float4*)(out + (((size_t)b << 10) + t) * FF);
    for (int i = threadIdx.x; i < FF / 4; i += blockDim.x) d[i] = s[i];
}

// ---------------- PTX wrappers -----------------------------------------------
__device__ __forceinline__ void ldsm_x4(uint32_t* r, uint32_t a) {
    asm volatile("ldmatrix.sync.aligned.m8n8.x4.shared.b16 {%0,%1,%2,%3}, [%4];"
        : "=r"(r[0]), "=r"(r[1]), "=r"(r[2]), "=r"(r[3]) : "r"(a));
}
__device__ __forceinline__ void ldsm_x4_t(uint32_t* r, uint32_t a) {
    asm volatile("ldmatrix.sync.aligned.m8n8.x4.trans.shared.b16 {%0,%1,%2,%3}, [%4];"
        : "=r"(r[0]), "=r"(r[1]), "=r"(r[2]), "=r"(r[3]) : "r"(a));
}
__device__ __forceinline__ void mma_bf16(float* c, const uint32_t* a, const uint32_t* b) {
    asm volatile("mma.sync.aligned.m16n8k16.row.col.f32.bf16.bf16.f32 "
        "{%0,%1,%2,%3},{%4,%5,%6,%7},{%8,%9},{%0,%1,%2,%3};"
        : "+f"(c[0]), "+f"(c[1]), "+f"(c[2]), "+f"(c[3])
        : "r"(a[0]), "r"(a[1]), "r"(a[2]), "r"(a[3]), "r"(b[0]), "r"(b[1]));
}
__device__ __forceinline__ void cp16(uint32_t s, const void* g) {
    asm volatile("cp.async.cg.shared.global [%0], [%1], 16;" :: "r"(s), "l"(g));
}
#define CP_COMMIT asm volatile("cp.async.commit_group;")
#define CP_WAIT1  asm volatile("cp.async.wait_group 1;")
#define CP_WAIT0  asm volatile("cp.async.wait_group 0;")

// ---------------- tensor-core split-bf16 GEMM --------------------------------
// C[M,N] = Ahi@Bhi + Ahi@Blo + Alo@Bhi + bias.  A row-major [M,K] bf16 (hi/lo),
// B row-major [K,N] bf16 (hi/lo), C fp32.  Tiles 128x128x32, 256 threads.
#define STG_A 10240               // 128 rows * 80B pitch (pitch-5-chunks: conflict-free ldmatrix)
#define STG_B 8192                // 32 rows * 256B, XOR-swizzled
#define STG_SZ (2*STG_A + 2*STG_B)
#define SMEM_MMA (2*STG_SZ)       // double-buffered: 73728 B

__global__ __launch_bounds__(256)
void k_mma(const __nv_bfloat16* __restrict__ Ah, const __nv_bfloat16* __restrict__ Al,
           const __nv_bfloat16* __restrict__ Bh, const __nv_bfloat16* __restrict__ Bl,
           const float* __restrict__ bias, float* __restrict__ C, int N, int K) {
    extern __shared__ char smem[];
    uint32_t su = (uint32_t)__cvta_generic_to_shared(smem);
    int tid = threadIdx.x, lane = tid & 31, wid = tid >> 5;
    int mw = wid & 3, nw = wid >> 2;          // 4x2 warp grid
    int m0 = blockIdx.y * 128, n0 = blockIdx.x * 128;

    float acc[2][8][4];
#pragma unroll
    for (int mi = 0; mi < 2; mi++)
#pragma unroll
        for (int j = 0; j < 8; j++)
#pragma unroll
            for (int q = 0; q < 4; q++) acc[mi][j][q] = 0.f;

    auto load_stage = [&](int st, int k0) {
        uint32_t sa = su + st * STG_SZ;
#pragma unroll
        for (int hl = 0; hl < 2; hl++) {
            const __nv_bfloat16* Ap = hl ? Al : Ah;
            uint32_t sb = sa + hl * STG_A;
#pragma unroll
            for (int rep = 0; rep < 2; rep++) {
                int idx = tid + rep * 256;          // 0..511
                int r = idx >> 2, c = idx & 3;
                cp16(sb + r * 80 + c * 16, Ap + (size_t)(m0 + r) * K + k0 + c * 8);
            }
        }
#pragma unroll
        for (int hl = 0; hl < 2; hl++) {
            const __nv_bfloat16* Bp = hl ? Bl : Bh;
            uint32_t sb = sa + 2 * STG_A + hl * STG_B;
#pragma unroll
            for (int rep = 0; rep < 2; rep++) {
                int idx = tid + rep * 256;
                int k = idx >> 4, c = idx & 15;
                cp16(sb + k * 256 + ((c ^ (k & 7)) * 16),
                     Bp + (size_t)(k0 + k) * N + n0 + c * 8);
            }
        }
    };

    int NIT = K >> 5;                             // 16 for K=512
    load_stage(0, 0);
    CP_COMMIT;

    for (int it = 0; it < NIT; it++) {
        if (it + 1 < NIT) { load_stage((it + 1) & 1, (it + 1) * 32); CP_COMMIT; CP_WAIT1; }
        else              { CP_WAIT0; }
        __syncthreads();

        uint32_t sa = su + (it & 1) * STG_SZ;
#pragma unroll
        for (int kk = 0; kk < 2; kk++) {
            uint32_t ah[2][4], al[2][4];
            int arow_c = kk * 2 + (lane >> 4);    // k-chunk within row
            int arow_r = (lane & 15);
#pragma unroll
            for (int mi = 0; mi < 2; mi++) {
                uint32_t ad = sa + (mw * 32 + mi * 16 + arow_r) * 80 + arow_c * 16;
                ldsm_x4(ah[mi], ad);
                ldsm_x4(al[mi], ad + STG_A);
            }
#pragma unroll
            for (int jp = 0; jp < 4; jp++) {
                int krow = kk * 16 + (lane & 15);
                int cch  = nw * 8 + jp * 2 + (lane >> 4);
                uint32_t bd = sa + 2 * STG_A + krow * 256 + ((cch ^ (krow & 7)) * 16);
                uint32_t bh[4], bl[4];
                ldsm_x4_t(bh, bd);
                ldsm_x4_t(bl, bd + STG_B);
#pragma unroll
                for (int jj = 0; jj < 2; jj++) {
#pragma unroll
                    for (int mi = 0; mi < 2; mi++) {
                        float* a4 = acc[mi][jp * 2 + jj];
                        mma_bf16(a4, ah[mi], &bh[jj * 2]);  // Ahi @ Bhi
                        mma_bf16(a4, ah[mi], &bl[jj * 2]);  // Ahi @ Blo
                        mma_bf16(a4, al[mi], &bh[jj * 2]);  // Alo @ Bhi
                    }
                }
            }
        }
        __syncthreads();
    }

    // epilogue: bias + store
#pragma unroll
    for (int mi = 0; mi < 2; mi++) {
#pragma unroll
        for (int j = 0; j < 8; j++) {
            int row = m0 + mw * 32 + mi * 16 + (lane >> 2);
            int col = n0 + nw * 64 + j * 8 + (lane & 3) * 2;
            float b0 = bias[col], b1 = bias[col + 1];
            float2 v0 = {acc[mi][j][0] + b0, acc[mi][j][1] + b1};
            float2 v1 = {acc[mi][j][2] + b0, acc[mi][j][3] + b1};
            *(float2*)(C + (size_t)row * N + col)       = v0;
            *(float2*)(C + (size_t)(row + 8) * N + col) = v1;
        }
    }
}

// ---------------- reset barrier + h buffers (before each recurrence) ---------
__global__ void k_reset() {
    int i = blockIdx.x * blockDim.x + threadIdx.x;
    if (i == 0) g_bar = 0u;
    float* gh = &g_h[0][0][0];
    if (i < 2 * 2 * HH * BB) gh[i] = 0.f;
}

// ---------------- persistent bidirectional highway-LSTM scan -----------------
#define REC_SMEM ((256 * 20 + 256 * 64) * 4)

__device__ __forceinline__ float sigf(float x) { return 1.f / (1.f + expf(-x)); }

__global__ __launch_bounds__(128, 1)
void k_rec(const float* __restrict__ Wh_l,   // [2][256][1280] (this layer)
           const float* __restrict__ bh_l,   // [2][1280]
           const float* __restrict__ gx0, const float* __restrict__ gx1,
           const float* __restrict__ px0, const float* __restrict__ px1,
           float* __restrict__ outbuf) {     // [t][b][512] (fwd|bwd concat)
    extern __shared__ float sm[];
    float* w_s = sm;                 // [256][20] Wh slice (gate-interleaved)
    float* h_s = sm + 256 * 20;      // [256 k][64 b] staged h_prev
    float* red = h_s;                // reused post-k-loop for kh reduction

    int tid = threadIdx.x;
    int d  = blockIdx.x & 1;
    int j  = blockIdx.x >> 1;
    int c  = tid & 3;
    int bq = (tid >> 2) & 15;
    int kh = tid >> 6;
    int col = j * 4 + c;
    int b0  = bq * 4;
    int be  = b0 + kh * 2;           // epilogue batches: be, be+1

    const float* Wh_d = Wh_l + (size_t)d * HH * GXN;
    const float* gx = d ? gx1 : gx0;
    const float* px = d ? px1 : px0;

    for (int idx = tid; idx < 256 * 20; idx += 128) {
        int k = idx / 20, gc = idx % 20;
        int g = gc >> 2, cc = gc & 3;
        w_s[idx] = Wh_d[(size_t)k * GXN + g * HH + j * 4 + cc];
    }
    float bh5[5];
#pragma unroll
    for (int g = 0; g < 5; g++) bh5[g] = bh_l[(size_t)d * GXN + g * HH + col];

    float cs0 = 0.f, cs1 = 0.f;
    __syncthreads();

    for (int s = 0; s < TT; s++) {
        int t = d ? (TT - 1 - s) : s;

        size_t r0 = ((size_t)t * BB + be) * GXN;
        float gxa[5], gxb[5];
#pragma unroll
        for (int g = 0; g < 5; g++) {
            gxa[g] = __ldg(gx + r0 + g * HH + col);
            gxb[g] = __ldg(gx + r0 + GXN + g * HH + col);
        }
        float pxa = __ldg(px + ((size_t)t * BB + be) * HH + col);
        float pxb = __ldg(px + ((size_t)t * BB + be + 1) * HH + col);

        {
            const float4* src = (const float4*)&g_h[s & 1][d][0];
            float4* dst = (float4*)h_s;
#pragma unroll
            for (int i = 0; i < 32; i++) dst[tid + i * 128] = __ldcg(&src[tid + i * 128]);
        }
        __syncthreads();

        float4 acc[5];
#pragma unroll
        for (int g = 0; g < 5; g++) acc[g] = make_float4(0.f, 0.f, 0.f, 0.f);
        int kb = kh * 128;
#pragma unroll 4
        for (int k = 0; k < 128; k++) {
            float4 hv = *(const float4*)&h_s[(kb + k) * BB + b0];
#pragma unroll
            for (int g = 0; g < 5; g++) {
                float w = w_s[(kb + k) * 20 + g * 4 + c];
                acc[g].x += hv.x * w;
                acc[g].y += hv.y * w;
                acc[g].z += hv.z * w;
                acc[g].w += hv.w * w;
            }
        }
        __syncthreads();

        int slot = (bq * 4 + c) * 10;
        float* myred = red + kh * 640 + slot;
        if (kh == 0) {
#pragma unroll
            for (int g = 0; g < 5; g++) { myred[g * 2] = acc[g].z; myred[g * 2 + 1] = acc[g].w; }
        } else {
#pragma unroll
            for (int g = 0; g < 5; g++) { myred[g * 2] = acc[g].x; myred[g * 2 + 1] = acc[g].y; }
        }
        __syncthreads();
        const float* pr = red + (1 - kh) * 640 + slot;
        float za[5], zb[5];
        if (kh == 0) {
#pragma unroll
            for (int g = 0; g < 5; g++) { za[g] = acc[g].x + pr[g * 2]; zb[g] = acc[g].y + pr[g * 2 + 1]; }
        } else {
#pragma unroll
            for (int g = 0; g < 5; g++) { za[g] = acc[g].z + pr[g * 2]; zb[g] = acc[g].w + pr[g * 2 + 1]; }
        }

        {
            float zi = za[0] + gxa[0] + bh5[0];
            float zo = za[1] + gxa[1] + bh5[1];
            float zf = za[2] + gxa[2] + bh5[2];
            float zu = za[3] + gxa[3] + bh5[3];
            float zr = za[4] + gxa[4] + bh5[4];
            cs0 = sigf(zi) * tanhf(zu) + sigf(zf) * cs0;
            float hhv = sigf(zo) * tanhf(cs0);
            float rg  = sigf(zr);
            float hf  = rg * hhv + (1.f - rg) * pxa;
            __stcg(&g_h[(s + 1) & 1][d][col * BB + be], hf);
            outbuf[((size_t)t * BB + be) * FF + d * HH + col] = hf;
        }
        {
            float zi = zb[0] + gxb[0] + bh5[0];
            float zo = zb[1] + gxb[1] + bh5[1];
            float zf = zb[2] + gxb[2] + bh5[2];
            float zu = zb[3] + gxb[3] + bh5[3];
            float zr = zb[4] + gxb[4] + bh5[4];
            cs1 = sigf(zi) * tanhf(zu) + sigf(zf) * cs1;
            float hhv = sigf(zo) * tanhf(cs1);
            float rg  = sigf(zr);
            float hf  = rg * hhv + (1.f - rg) * pxb;
            __stcg(&g_h[(s + 1) & 1][d][col * BB + be + 1], hf);
            outbuf[((size_t)t * BB + be + 1) * FF + d * HH + col] = hf;
        }

        __threadfence();
        __syncthreads();
        if (tid == 0) {
            atomicAdd(&g_bar, 1u);
            unsigned target = (unsigned)(s + 1) * NBLK;
            volatile unsigned* vb = &g_bar;
            while (*vb < target) __nanosleep(40);
        }
        __syncthreads();
    }
}

// ---------------------------- host driver ------------------------------------
extern "C" void kernel_launch(void* const* d_in, const int* in_sizes, int n_in,
                              void* d_out, int out_size) {
    (void)in_sizes; (void)n_in; (void)out_size;
    const float* feat = (const float*)d_in[0];
    const float* Wx   = (const float*)d_in[1];  // [2][2][512][1280]
    const float* bx   = (const float*)d_in[2];  // [2][2][1280]
    const float* Wh   = (const float*)d_in[3];  // [2][2][256][1280]
    const float* bh   = (const float*)d_in[4];  // [2][2][1280]
    const float* Wp   = (const float*)d_in[5];  // [2][2][512][256]
    const float* bp   = (const float*)d_in[6];  // [2][2][256]
    float* out = (float*)d_out;

    float *p_y, *p_f, *p_gx, *p_px;
    __nv_bfloat16 *p_xh, *p_xl, *p_yh, *p_yl, *p_wxh, *p_wxl, *p_wph, *p_wpl;
    cudaGetSymbolAddress((void**)&p_y,   g_y);
    cudaGetSymbolAddress((void**)&p_f,   g_fin);
    cudaGetSymbolAddress((void**)&p_gx,  g_gx);
    cudaGetSymbolAddress((void**)&p_px,  g_px);
    cudaGetSymbolAddress((void**)&p_xh,  g_xh);
    cudaGetSymbolAddress((void**)&p_xl,  g_xl);
    cudaGetSymbolAddress((void**)&p_yh,  g_yh);
    cudaGetSymbolAddress((void**)&p_yl,  g_yl);
    cudaGetSymbolAddress((void**)&p_wxh, g_wxh);
    cudaGetSymbolAddress((void**)&p_wxl, g_wxl);
    cudaGetSymbolAddress((void**)&p_wph, g_wph);
    cudaGetSymbolAddress((void**)&p_wpl, g_wpl);

    cudaFuncSetAttribute(k_rec, cudaFuncAttributeMaxDynamicSharedMemorySize, REC_SMEM);
    cudaFuncSetAttribute(k_mma, cudaFuncAttributeMaxDynamicSharedMemorySize, SMEM_MMA);

    const size_t GXSZ = (size_t)TT * BB * GXN;
    const size_t PXSZ = (size_t)TT * BB * HH;

    // input transpose + split, weight splits
    k_tin<<<TT * BB, 128>>>(feat, p_xh, p_xl);
    k_split<<<(2 * 2 * FF * GXN / 4 + 255) / 256, 256>>>(Wx, p_wxh, p_wxl, 2 * 2 * FF * GXN / 4);
    k_split<<<(2 * 2 * FF * HH  / 4 + 255) / 256, 256>>>(Wp, p_wph, p_wpl, 2 * 2 * FF * HH / 4);

    for (int l = 0; l < 2; l++) {
        const __nv_bfloat16* Ah = l ? p_yh : p_xh;
        const __nv_bfloat16* Al = l ? p_yl : p_xl;
        float* OUT = l ? p_f : p_y;
        for (int dd = 0; dd < 2; dd++) {
            int w = l * 2 + dd;
            k_mma<<<dim3(GXN / 128, (TT * BB) / 128), 256, SMEM_MMA>>>(
                Ah, Al, p_wxh + (size_t)w * FF * GXN, p_wxl + (size_t)w * FF * GXN,
                bx + (size_t)w * GXN, p_gx + dd * GXSZ, GXN, FF);
            k_mma<<<dim3(HH / 128, (TT * BB) / 128), 256, SMEM_MMA>>>(
                Ah, Al, p_wph + (size_t)w * FF * HH, p_wpl + (size_t)w * FF * HH,
                bp + (size_t)w * HH, p_px + dd * PXSZ, HH, FF);
        }
        k_reset<<<256, 256>>>();
        k_rec<<<NBLK, 128, REC_SMEM>>>(
            Wh + (size_t)l * 2 * HH * GXN, bh + (size_t)l * 2 * GXN,
            p_gx, p_gx + GXSZ, p_px, p_px + PXSZ, OUT);
        if (l == 0)
            k_split<<<(TT * BB * FF / 4) / 256, 256>>>(p_y, p_yh, p_yl, TT * BB * FF / 4);
    }

    k_tout<<<TT * BB, 128>>>(p_f, out);
}